// round 9
// baseline (speedup 1.0000x reference)
#include <cuda_runtime.h>
#include <cuda_fp16.h>
#include <cstdint>

#define NB   8
#define QDIM 2048
#define KDIM 2048
#define EDIM 512

typedef __half fp16;

// ---------------------------------------------------------------------------
// Device-global scratch (allocation-guard-safe)
// ---------------------------------------------------------------------------
__device__ __align__(256) fp16  g_Qh[(size_t)NB * QDIM * EDIM];
__device__ __align__(256) fp16  g_Ql[(size_t)NB * QDIM * EDIM];
__device__ __align__(256) fp16  g_Kh[(size_t)NB * KDIM * EDIM];
__device__ __align__(256) fp16  g_Kl[(size_t)NB * KDIM * EDIM];
__device__ __align__(256) fp16  g_Vth[(size_t)NB * EDIM * KDIM];  // V^T [b][e][k]
__device__ __align__(256) fp16  g_Vtl[(size_t)NB * EDIM * KDIM];
__device__ __align__(256) float g_E  [(size_t)NB * QDIM * KDIM];  // logits
__device__ __align__(256) fp16  g_Ph [(size_t)NB * QDIM * KDIM];  // softmax (hi only)

// ---------------------------------------------------------------------------
// PTX helpers (plain sm_80+ features only — virtual arch is compute_103)
// ---------------------------------------------------------------------------
__device__ __forceinline__ uint32_t smem_u32(const void* p) {
    uint32_t a;
    asm("{ .reg .u64 t; cvta.to.shared.u64 t, %1; cvt.u32.u64 %0, t; }" : "=r"(a) : "l"(p));
    return a;
}

__device__ __forceinline__ uint32_t h2_u32(__half2 h) {
    union { __half2 h; uint32_t u; } c;
    c.h = h;
    return c.u;
}

#define CP_ASYNC16(dst, src) \
    asm volatile("cp.async.cg.shared.global [%0], [%1], 16;" :: "r"(dst), "l"(src))
#define CP_COMMIT() asm volatile("cp.async.commit_group;" ::: "memory")
#define CP_WAIT1()  asm volatile("cp.async.wait_group 1;" ::: "memory")
#define CP_WAIT0()  asm volatile("cp.async.wait_group 0;" ::: "memory")

#define LDSM_X4(r0, r1, r2, r3, a)                                          \
    asm volatile("ldmatrix.sync.aligned.m8n8.x4.shared.b16 {%0,%1,%2,%3}, [%4];" \
        : "=r"(r0), "=r"(r1), "=r"(r2), "=r"(r3) : "r"(a))

#define MMA16816(d, a, b0, b1)                                              \
    asm volatile("mma.sync.aligned.m16n8k16.row.col.f32.f16.f16.f32 "       \
        "{%0,%1,%2,%3},{%4,%5,%6,%7},{%8,%9},{%0,%1,%2,%3};"                \
        : "+f"((d)[0]), "+f"((d)[1]), "+f"((d)[2]), "+f"((d)[3])            \
        : "r"((a)[0]), "r"((a)[1]), "r"((a)[2]), "r"((a)[3]),               \
          "r"(b0), "r"(b1))

// ---------------------------------------------------------------------------
// Elementwise fp32 -> fp16 hi/lo split  (which: 0 = Q, 1 = K)
// ---------------------------------------------------------------------------
__global__ __launch_bounds__(256)
void split_kernel(const float* __restrict__ X, int which, int n4)
{
    fp16* Xh = which ? g_Kh : g_Qh;
    fp16* Xl = which ? g_Kl : g_Ql;
    int i = blockIdx.x * 256 + threadIdx.x;
    if (i >= n4) return;
    float4 v = ((const float4*)X)[i];
    fp16 h0 = __float2half_rn(v.x), h1 = __float2half_rn(v.y);
    fp16 h2 = __float2half_rn(v.z), h3 = __float2half_rn(v.w);
    fp16 l0 = __float2half_rn(v.x - __half2float(h0));
    fp16 l1 = __float2half_rn(v.y - __half2float(h1));
    fp16 l2 = __float2half_rn(v.z - __half2float(h2));
    fp16 l3 = __float2half_rn(v.w - __half2float(h3));
    ((__half2*)Xh)[2 * i]     = __half2(h0, h1);
    ((__half2*)Xh)[2 * i + 1] = __half2(h2, h3);
    ((__half2*)Xl)[2 * i]     = __half2(l0, l1);
    ((__half2*)Xl)[2 * i + 1] = __half2(l2, l3);
}

// ---------------------------------------------------------------------------
// V [b][k][e] fp32 -> V^T [b][e][k] fp16 hi/lo
// ---------------------------------------------------------------------------
__global__ __launch_bounds__(256)
void vtrans_kernel(const float* __restrict__ V)
{
    __shared__ float t[32][33];
    const int b  = blockIdx.z;
    const int k0 = blockIdx.x * 32;
    const int e0 = blockIdx.y * 32;
    const int tx = threadIdx.x & 31;
    const int ty = threadIdx.x >> 5;
    const float* Vb = V + (size_t)b * KDIM * EDIM;

    #pragma unroll
    for (int j = 0; j < 4; j++)
        t[ty + j * 8][tx] = Vb[(size_t)(k0 + ty + j * 8) * EDIM + e0 + tx];
    __syncthreads();

    #pragma unroll
    for (int j = 0; j < 4; j++) {
        int e = e0 + ty + j * 8;
        int k = k0 + tx;
        float x = t[tx][ty + j * 8];
        fp16 h = __float2half_rn(x);
        fp16 l = __float2half_rn(x - __half2float(h));
        size_t o = (size_t)b * EDIM * KDIM + (size_t)e * KDIM + k;
        g_Vth[o] = h;
        g_Vtl[o] = l;
    }
}

// ---------------------------------------------------------------------------
// Row softmax of g_E -> fp16 (hi only) in g_Ph  (float4 I/O)
// ---------------------------------------------------------------------------
__global__ __launch_bounds__(256)
void softmax_split_kernel()
{
    const size_t row = blockIdx.x;
    const float* p = g_E + row * (size_t)KDIM;
    const int tid = threadIdx.x;

    float4 va = ((const float4*)p)[tid];
    float4 vb = ((const float4*)p)[tid + 256];

    float m = fmaxf(fmaxf(fmaxf(va.x, va.y), fmaxf(va.z, va.w)),
                    fmaxf(fmaxf(vb.x, vb.y), fmaxf(vb.z, vb.w)));

    __shared__ float red[8];
    #pragma unroll
    for (int off = 16; off > 0; off >>= 1) m = fmaxf(m, __shfl_xor_sync(~0u, m, off));
    if ((tid & 31) == 0) red[tid >> 5] = m;
    __syncthreads();
    if (tid < 8) {
        float t = red[tid];
        #pragma unroll
        for (int off = 4; off > 0; off >>= 1) t = fmaxf(t, __shfl_xor_sync(0xFFu, t, off));
        red[tid] = t;
    }
    __syncthreads();
    m = red[0];

    va.x = __expf(va.x - m); va.y = __expf(va.y - m);
    va.z = __expf(va.z - m); va.w = __expf(va.w - m);
    vb.x = __expf(vb.x - m); vb.y = __expf(vb.y - m);
    vb.z = __expf(vb.z - m); vb.w = __expf(vb.w - m);
    float s = (va.x + va.y) + (va.z + va.w) + (vb.x + vb.y) + (vb.z + vb.w);

    __shared__ float red2[8];
    #pragma unroll
    for (int off = 16; off > 0; off >>= 1) s += __shfl_xor_sync(~0u, s, off);
    if ((tid & 31) == 0) red2[tid >> 5] = s;
    __syncthreads();
    if (tid < 8) {
        float t = red2[tid];
        #pragma unroll
        for (int off = 4; off > 0; off >>= 1) t += __shfl_xor_sync(0xFFu, t, off);
        red2[tid] = t;
    }
    __syncthreads();
    const float inv = 1.0f / red2[0];

    fp16* ph = g_Ph + row * (size_t)KDIM;
    __half2 hh[4];
    hh[0] = __half2(__float2half_rn(va.x * inv), __float2half_rn(va.y * inv));
    hh[1] = __half2(__float2half_rn(va.z * inv), __float2half_rn(va.w * inv));
    hh[2] = __half2(__float2half_rn(vb.x * inv), __float2half_rn(vb.y * inv));
    hh[3] = __half2(__float2half_rn(vb.z * inv), __float2half_rn(vb.w * inv));
    *(uint2*)&ph[tid * 4]        = make_uint2(h2_u32(hh[0]), h2_u32(hh[1]));
    *(uint2*)&ph[1024 + tid * 4] = make_uint2(h2_u32(hh[2]), h2_u32(hh[3]));
}

// ---------------------------------------------------------------------------
// HMMA split-fp16 GEMM: 2 CTAs/SM + double-buffered cp.async ring.
//   MODE 0 (3 passes): E = Q.K^T   A = Qh/Ql [2048x512], B = Kh/Kl [2048x512]
//   MODE 1 (2 passes): O = P.V     A = Ph [2048x2048],  B = Vth/Vtl [512x2048]
// CTA tile 128x128, 256 threads (8 warps, 2x4 grid), warp tile 64x32.
// K-chunk 32. Tiles are 128 rows x 32 fp16 stored at an 80-byte row pitch:
// start-bank = (5r + c) mod 8 -> ldmatrix phases conflict-free, 16B stores
// uniformly 4-way (optimal). No xor swizzle needed.
// ---------------------------------------------------------------------------
#define PITCH   80u
#define TILE_P  (128u * PITCH)      // 10240 bytes per 128x32 tile

// Copy one 128x32 fp16 tile (row-major, stride ld halfs) into pitched smem.
__device__ __forceinline__ void cp_tile(uint32_t dstbase, const fp16* src,
                                        int ld, int tid)
{
    const char* s = (const char*)src;
    const size_t row_bytes = (size_t)ld * 2;
    // 512 16B-chunks (128 rows x 4 chunks), 256 threads -> 2 each.
    #pragma unroll
    for (int pass = 0; pass < 2; ++pass) {
        int idx = tid + pass * 256;
        int r = idx & 127;
        int c = idx >> 7;               // 0..3
        uint32_t dst = dstbase + (uint32_t)r * PITCH + (uint32_t)c * 16u;
        CP_ASYNC16(dst, s + (size_t)r * row_bytes + c * 16);
    }
}

__device__ __forceinline__ void lds_a(uint32_t base, int kk, int wm,
                                      int a_r15, int c_hi, uint32_t af[4][4])
{
    #pragma unroll
    for (int mi = 0; mi < 4; ++mi) {
        const int row = wm + mi * 16 + a_r15;
        const uint32_t addr = base + (uint32_t)row * PITCH
            + (uint32_t)((kk * 2 + c_hi) << 4);
        LDSM_X4(af[mi][0], af[mi][1], af[mi][2], af[mi][3], addr);
    }
}

__device__ __forceinline__ void lds_b(uint32_t base, int kk, int wn,
                                      int a_r15, int c_hi, uint32_t bf[2][4])
{
    #pragma unroll
    for (int nj = 0; nj < 2; ++nj) {
        const int row = wn + nj * 16 + a_r15;
        const uint32_t addr = base + (uint32_t)row * PITCH
            + (uint32_t)((kk * 2 + c_hi) << 4);
        LDSM_X4(bf[nj][0], bf[nj][1], bf[nj][2], bf[nj][3], addr);
    }
}

__device__ __forceinline__ void mma_step(float acc[4][4][4],
                                         uint32_t af[4][4], uint32_t bf[2][4])
{
    #pragma unroll
    for (int mi = 0; mi < 4; ++mi) {
        #pragma unroll
        for (int ni = 0; ni < 4; ++ni) {
            const uint32_t b0 = bf[ni >> 1][(ni & 1) ? 1 : 0];
            const uint32_t b1 = bf[ni >> 1][(ni & 1) ? 3 : 2];
            MMA16816(acc[mi][ni], af[mi], b0, b1);
        }
    }
}

template <int MODE>
__global__ __launch_bounds__(256, 2)
void hgemm3_kernel(float* __restrict__ Oout)
{
    constexpr int LDA  = (MODE == 0) ? EDIM : KDIM;
    constexpr int LDB  = (MODE == 0) ? EDIM : KDIM;
    constexpr int LDC  = (MODE == 0) ? KDIM : EDIM;
    constexpr int KTOT = (MODE == 0) ? EDIM : KDIM;
    constexpr size_t SA = (MODE == 0) ? (size_t)QDIM * EDIM : (size_t)QDIM * KDIM;
    constexpr size_t SB = (MODE == 0) ? (size_t)KDIM * EDIM : (size_t)EDIM * KDIM;
    constexpr size_t SC = (MODE == 0) ? (size_t)QDIM * KDIM : (size_t)QDIM * EDIM;
    constexpr int NITER = KTOT / 32;

    // Stage layout: A_hi [A_lo] B_hi B_lo  (10240 B pitched tiles)
    constexpr uint32_t OFF_AH = 0;
    constexpr uint32_t OFF_AL = TILE_P;                         // MODE 0 only
    constexpr uint32_t OFF_BH = (MODE == 0) ? 2 * TILE_P : TILE_P;
    constexpr uint32_t OFF_BL = OFF_BH + TILE_P;
    constexpr uint32_t STAGE  = OFF_BL + TILE_P;                // 40960 / 30720

    extern __shared__ __align__(256) uint8_t smem[];
    const uint32_t sb = smem_u32(smem);

    const int tid  = threadIdx.x;
    const int lane = tid & 31;
    const int wid  = tid >> 5;                   // 0..7
    const int wm   = (wid >> 2) * 64;            // 0 or 64
    const int wn   = (wid & 3) * 32;             // 0..96
    const int b    = blockIdx.z;
    const int m0   = blockIdx.y * 128;
    const int n0   = blockIdx.x * 128;

    const fp16* Ah = ((MODE == 0) ? g_Qh : g_Ph)  + b * SA + (size_t)m0 * LDA;
    const fp16* Al = g_Ql + b * SA + (size_t)m0 * LDA;          // MODE 0 only
    const fp16* Bh = ((MODE == 0) ? g_Kh : g_Vth) + b * SB + (size_t)n0 * LDB;
    const fp16* Bl = ((MODE == 0) ? g_Kl : g_Vtl) + b * SB + (size_t)n0 * LDB;
    float* C = ((MODE == 0) ? g_E : Oout) + b * SC;

    float acc[4][4][4];
    #pragma unroll
    for (int i = 0; i < 4; i++)
        #pragma unroll
        for (int j = 0; j < 4; j++)
            #pragma unroll
            for (int q = 0; q < 4; q++) acc[i][j][q] = 0.0f;

    const int a_r15 = lane & 15;
    const int c_hi  = lane >> 4;

    // Prologue: fill both stages (chunks 0 and 1)
    cp_tile(sb + OFF_AH, Ah, LDA, tid);
    if (MODE == 0) cp_tile(sb + OFF_AL, Al, LDA, tid);
    cp_tile(sb + OFF_BH, Bh, LDB, tid);
    cp_tile(sb + OFF_BL, Bl, LDB, tid);
    CP_COMMIT();
    {
        const uint32_t nb = sb + STAGE;
        cp_tile(nb + OFF_AH, Ah + 32, LDA, tid);
        if (MODE == 0) cp_tile(nb + OFF_AL, Al + 32, LDA, tid);
        cp_tile(nb + OFF_BH, Bh + 32, LDB, tid);
        cp_tile(nb + OFF_BL, Bl + 32, LDB, tid);
        CP_COMMIT();
    }

    for (int it = 0; it < NITER; ++it) {
        if (it + 1 < NITER) CP_WAIT1(); else CP_WAIT0();
        __syncthreads();                         // chunk it visible to all

        const uint32_t SBASE = sb + (it & 1) * STAGE;

        #pragma unroll
        for (int kk = 0; kk < 2; ++kk) {
            uint32_t af[4][4], bfh[2][4], bfl[2][4];
            lds_a(SBASE + OFF_AH, kk, wm, a_r15, c_hi, af);   // A hi
            lds_b(SBASE + OFF_BH, kk, wn, a_r15, c_hi, bfh);  // B hi
            lds_b(SBASE + OFF_BL, kk, wn, a_r15, c_hi, bfl);  // B lo
            mma_step(acc, af, bfh);                            // Ah*Bh
            mma_step(acc, af, bfl);                            // Ah*Bl
            if (MODE == 0) {
                lds_a(SBASE + OFF_AL, kk, wm, a_r15, c_hi, af);  // A lo
                mma_step(acc, af, bfh);                           // Al*Bh
            }
        }
        __syncthreads();                         // stage drained by all warps

        if (it + 2 < NITER) {                    // refill this stage (chunk it+2)
            const int k0 = (it + 2) * 32;
            cp_tile(SBASE + OFF_AH, Ah + k0, LDA, tid);
            if (MODE == 0) cp_tile(SBASE + OFF_AL, Al + k0, LDA, tid);
            cp_tile(SBASE + OFF_BH, Bh + k0, LDB, tid);
            cp_tile(SBASE + OFF_BL, Bl + k0, LDB, tid);
            CP_COMMIT();
        }
    }

    // Epilogue
    const int g  = lane >> 2;
    const int ti = lane & 3;
    #pragma unroll
    for (int mi = 0; mi < 4; ++mi) {
        #pragma unroll
        for (int ni = 0; ni < 4; ++ni) {
            const int row = m0 + wm + mi * 16 + g;
            const int col = n0 + wn + ni * 8 + ti * 2;
            *(float2*)&C[(size_t)row * LDC + col] =
                make_float2(acc[mi][ni][0], acc[mi][ni][1]);
            *(float2*)&C[(size_t)(row + 8) * LDC + col] =
                make_float2(acc[mi][ni][2], acc[mi][ni][3]);
        }
    }
}

// ---------------------------------------------------------------------------
extern "C" void kernel_launch(void* const* d_in, const int* in_sizes, int n_in,
                              void* d_out, int out_size)
{
    const float* Q = (const float*)d_in[0];
    const float* K = (const float*)d_in[1];
    const float* V = (const float*)d_in[2];
    float*       O = (float*)d_out;

    // MODE 0: 2 stages x 4 tiles x 10240B = 81920;  MODE 1: 2 x 3 x 10240 = 61440
    cudaFuncSetAttribute(hgemm3_kernel<0>, cudaFuncAttributeMaxDynamicSharedMemorySize, 81920);
    cudaFuncSetAttribute(hgemm3_kernel<1>, cudaFuncAttributeMaxDynamicSharedMemorySize, 61440);

    const int n4 = NB * QDIM * EDIM / 4;
    split_kernel<<<(n4 + 255) / 256, 256>>>(Q, 0, n4);
    split_kernel<<<(n4 + 255) / 256, 256>>>(K, 1, n4);
    vtrans_kernel<<<dim3(KDIM / 32, EDIM / 32, NB), 256>>>(V);

    hgemm3_kernel<0><<<dim3(KDIM / 128, QDIM / 128, NB), 256, 81920>>>(nullptr);

    softmax_split_kernel<<<NB * QDIM, 256>>>();

    hgemm3_kernel<1><<<dim3(EDIM / 128, QDIM / 128, NB), 256, 61440>>>(O);
}

// round 10
// speedup vs baseline: 1.5701x; 1.5701x over previous
#include <cuda_runtime.h>
#include <cuda_fp16.h>
#include <cstdint>

#define NB   8
#define QDIM 2048
#define KDIM 2048
#define EDIM 512

typedef __half fp16;

// ---------------------------------------------------------------------------
// Device-global scratch (allocation-guard-safe)
// ---------------------------------------------------------------------------
__device__ __align__(256) fp16  g_Qh[(size_t)NB * QDIM * EDIM];
__device__ __align__(256) fp16  g_Ql[(size_t)NB * QDIM * EDIM];
__device__ __align__(256) fp16  g_Kh[(size_t)NB * KDIM * EDIM];
__device__ __align__(256) fp16  g_Kl[(size_t)NB * KDIM * EDIM];
__device__ __align__(256) fp16  g_Vth[(size_t)NB * EDIM * KDIM];  // V^T [b][e][k]
__device__ __align__(256) fp16  g_Vtl[(size_t)NB * EDIM * KDIM];
__device__ __align__(256) float g_E  [(size_t)NB * QDIM * KDIM];  // logits
__device__ __align__(256) fp16  g_Ph [(size_t)NB * QDIM * KDIM];  // softmax (hi only)

// ---------------------------------------------------------------------------
// PTX helpers (plain sm_80+ features only — virtual arch is compute_103)
// ---------------------------------------------------------------------------
__device__ __forceinline__ uint32_t smem_u32(const void* p) {
    uint32_t a;
    asm("{ .reg .u64 t; cvta.to.shared.u64 t, %1; cvt.u32.u64 %0, t; }" : "=r"(a) : "l"(p));
    return a;
}

__device__ __forceinline__ uint32_t h2_u32(__half2 h) {
    union { __half2 h; uint32_t u; } c;
    c.h = h;
    return c.u;
}

#define CP_ASYNC16(dst, src) \
    asm volatile("cp.async.cg.shared.global [%0], [%1], 16;" :: "r"(dst), "l"(src))
#define CP_COMMIT() asm volatile("cp.async.commit_group;" ::: "memory")
#define CP_WAIT1()  asm volatile("cp.async.wait_group 1;" ::: "memory")
#define CP_WAIT0()  asm volatile("cp.async.wait_group 0;" ::: "memory")

#define LDSM_X4(r0, r1, r2, r3, a)                                          \
    asm volatile("ldmatrix.sync.aligned.m8n8.x4.shared.b16 {%0,%1,%2,%3}, [%4];" \
        : "=r"(r0), "=r"(r1), "=r"(r2), "=r"(r3) : "r"(a))

#define MMA16816(d, a, b0, b1)                                              \
    asm volatile("mma.sync.aligned.m16n8k16.row.col.f32.f16.f16.f32 "       \
        "{%0,%1,%2,%3},{%4,%5,%6,%7},{%8,%9},{%0,%1,%2,%3};"                \
        : "+f"((d)[0]), "+f"((d)[1]), "+f"((d)[2]), "+f"((d)[3])            \
        : "r"((a)[0]), "r"((a)[1]), "r"((a)[2]), "r"((a)[3]),               \
          "r"(b0), "r"(b1))

// ---------------------------------------------------------------------------
// Elementwise fp32 -> fp16 hi/lo split  (which: 0 = Q, 1 = K)
// ---------------------------------------------------------------------------
__global__ __launch_bounds__(256)
void split_kernel(const float* __restrict__ X, int which, int n4)
{
    fp16* Xh = which ? g_Kh : g_Qh;
    fp16* Xl = which ? g_Kl : g_Ql;
    int i = blockIdx.x * 256 + threadIdx.x;
    if (i >= n4) return;
    float4 v = ((const float4*)X)[i];
    fp16 h0 = __float2half_rn(v.x), h1 = __float2half_rn(v.y);
    fp16 h2 = __float2half_rn(v.z), h3 = __float2half_rn(v.w);
    fp16 l0 = __float2half_rn(v.x - __half2float(h0));
    fp16 l1 = __float2half_rn(v.y - __half2float(h1));
    fp16 l2 = __float2half_rn(v.z - __half2float(h2));
    fp16 l3 = __float2half_rn(v.w - __half2float(h3));
    ((__half2*)Xh)[2 * i]     = __half2(h0, h1);
    ((__half2*)Xh)[2 * i + 1] = __half2(h2, h3);
    ((__half2*)Xl)[2 * i]     = __half2(l0, l1);
    ((__half2*)Xl)[2 * i + 1] = __half2(l2, l3);
}

// ---------------------------------------------------------------------------
// V [b][k][e] fp32 -> V^T [b][e][k] fp16 hi/lo
// ---------------------------------------------------------------------------
__global__ __launch_bounds__(256)
void vtrans_kernel(const float* __restrict__ V)
{
    __shared__ float t[32][33];
    const int b  = blockIdx.z;
    const int k0 = blockIdx.x * 32;
    const int e0 = blockIdx.y * 32;
    const int tx = threadIdx.x & 31;
    const int ty = threadIdx.x >> 5;
    const float* Vb = V + (size_t)b * KDIM * EDIM;

    #pragma unroll
    for (int j = 0; j < 4; j++)
        t[ty + j * 8][tx] = Vb[(size_t)(k0 + ty + j * 8) * EDIM + e0 + tx];
    __syncthreads();

    #pragma unroll
    for (int j = 0; j < 4; j++) {
        int e = e0 + ty + j * 8;
        int k = k0 + tx;
        float x = t[tx][ty + j * 8];
        fp16 h = __float2half_rn(x);
        fp16 l = __float2half_rn(x - __half2float(h));
        size_t o = (size_t)b * EDIM * KDIM + (size_t)e * KDIM + k;
        g_Vth[o] = h;
        g_Vtl[o] = l;
    }
}

// ---------------------------------------------------------------------------
// Row softmax of g_E -> fp16 (hi only) in g_Ph  (float4 I/O)
// ---------------------------------------------------------------------------
__global__ __launch_bounds__(256)
void softmax_split_kernel()
{
    const size_t row = blockIdx.x;
    const float* p = g_E + row * (size_t)KDIM;
    const int tid = threadIdx.x;

    float4 va = ((const float4*)p)[tid];
    float4 vb = ((const float4*)p)[tid + 256];

    float m = fmaxf(fmaxf(fmaxf(va.x, va.y), fmaxf(va.z, va.w)),
                    fmaxf(fmaxf(vb.x, vb.y), fmaxf(vb.z, vb.w)));

    __shared__ float red[8];
    #pragma unroll
    for (int off = 16; off > 0; off >>= 1) m = fmaxf(m, __shfl_xor_sync(~0u, m, off));
    if ((tid & 31) == 0) red[tid >> 5] = m;
    __syncthreads();
    if (tid < 8) {
        float t = red[tid];
        #pragma unroll
        for (int off = 4; off > 0; off >>= 1) t = fmaxf(t, __shfl_xor_sync(0xFFu, t, off));
        red[tid] = t;
    }
    __syncthreads();
    m = red[0];

    va.x = __expf(va.x - m); va.y = __expf(va.y - m);
    va.z = __expf(va.z - m); va.w = __expf(va.w - m);
    vb.x = __expf(vb.x - m); vb.y = __expf(vb.y - m);
    vb.z = __expf(vb.z - m); vb.w = __expf(vb.w - m);
    float s = (va.x + va.y) + (va.z + va.w) + (vb.x + vb.y) + (vb.z + vb.w);

    __shared__ float red2[8];
    #pragma unroll
    for (int off = 16; off > 0; off >>= 1) s += __shfl_xor_sync(~0u, s, off);
    if ((tid & 31) == 0) red2[tid >> 5] = s;
    __syncthreads();
    if (tid < 8) {
        float t = red2[tid];
        #pragma unroll
        for (int off = 4; off > 0; off >>= 1) t += __shfl_xor_sync(0xFFu, t, off);
        red2[tid] = t;
    }
    __syncthreads();
    const float inv = 1.0f / red2[0];

    fp16* ph = g_Ph + row * (size_t)KDIM;
    __half2 hh[4];
    hh[0] = __half2(__float2half_rn(va.x * inv), __float2half_rn(va.y * inv));
    hh[1] = __half2(__float2half_rn(va.z * inv), __float2half_rn(va.w * inv));
    hh[2] = __half2(__float2half_rn(vb.x * inv), __float2half_rn(vb.y * inv));
    hh[3] = __half2(__float2half_rn(vb.z * inv), __float2half_rn(vb.w * inv));
    *(uint2*)&ph[tid * 4]        = make_uint2(h2_u32(hh[0]), h2_u32(hh[1]));
    *(uint2*)&ph[1024 + tid * 4] = make_uint2(h2_u32(hh[2]), h2_u32(hh[3]));
}

// ---------------------------------------------------------------------------
// HMMA split-fp16 GEMM: 2 CTAs/SM + pipelined cp.async ring (coalesced fills).
//   MODE 0 (3 passes): E = Q.K^T. K-chunk 32. Packed rows: 128B = [hi32|lo32].
//                      Stage = A-pack(16K) + B-pack(16K) = 32KB. 3 stages.
//   MODE 1 (2 passes): O = P.V.  K-chunk 64. Tiles Ph / Vh / Vl, 128B rows.
//                      Stage = 3 x 16KB = 48KB. 2 stages.
// CTA tile 128x128, 256 threads (8 warps, 2x4), warp tile 64x32,
// __launch_bounds__(256,2) -> 2 CTAs/SM. 96KB smem/CTA both modes.
// ---------------------------------------------------------------------------
#define TILE16K 16384u

// Packed fill (MODE 0): 128 rows x [64B from srcH | 64B from srcL], swizzled.
// Consecutive threads -> consecutive 16B chunks (coalesced).
__device__ __forceinline__ void cp_pack(uint32_t dstbase, const fp16* srcH,
                                        const fp16* srcL, int ld, int tid)
{
    const char* sh = (const char*)srcH;
    const char* sl = (const char*)srcL;
    const size_t row_bytes = (size_t)ld * 2;
    #pragma unroll
    for (int p = 0; p < 4; ++p) {
        int idx = tid + p * 256;                 // 0..1023
        int r = idx >> 3;                        // row 0..127
        int c = idx & 7;                         // chunk 0..7
        const char* src = (c < 4) ? sh + (size_t)r * row_bytes + c * 16
                                  : sl + (size_t)r * row_bytes + (c - 4) * 16;
        uint32_t dst = dstbase + (uint32_t)r * 128u + (uint32_t)((c ^ (r & 7)) << 4);
        CP_ASYNC16(dst, src);
    }
}

// Plain fill (MODE 1): 128 rows x 128B from one source, swizzled, coalesced.
__device__ __forceinline__ void cp_tile(uint32_t dstbase, const fp16* src,
                                        int ld, int tid)
{
    const char* s = (const char*)src;
    const size_t row_bytes = (size_t)ld * 2;
    const int c = tid & 7;
    #pragma unroll
    for (int r0 = 0; r0 < 128; r0 += 32) {
        int r = r0 + (tid >> 3);
        uint32_t dst = dstbase + (uint32_t)r * 128u + (uint32_t)((c ^ (r & 7)) << 4);
        CP_ASYNC16(dst, s + (size_t)r * row_bytes + c * 16);
    }
}

// LDSM at 16B-chunk index cbase (+c_hi), xor-swizzled within 128B rows.
__device__ __forceinline__ void lds_a(uint32_t base, int cbase, int wm,
                                      int a_r15, int c_hi, uint32_t af[4][4])
{
    #pragma unroll
    for (int mi = 0; mi < 4; ++mi) {
        const int row = wm + mi * 16 + a_r15;
        const uint32_t addr = base + (uint32_t)row * 128u
            + (uint32_t)(((cbase + c_hi) ^ (row & 7)) << 4);
        LDSM_X4(af[mi][0], af[mi][1], af[mi][2], af[mi][3], addr);
    }
}

__device__ __forceinline__ void lds_b(uint32_t base, int cbase, int wn,
                                      int a_r15, int c_hi, uint32_t bf[2][4])
{
    #pragma unroll
    for (int nj = 0; nj < 2; ++nj) {
        const int row = wn + nj * 16 + a_r15;
        const uint32_t addr = base + (uint32_t)row * 128u
            + (uint32_t)(((cbase + c_hi) ^ (row & 7)) << 4);
        LDSM_X4(bf[nj][0], bf[nj][1], bf[nj][2], bf[nj][3], addr);
    }
}

__device__ __forceinline__ void mma_step(float acc[4][4][4],
                                         uint32_t af[4][4], uint32_t bf[2][4])
{
    #pragma unroll
    for (int mi = 0; mi < 4; ++mi) {
        #pragma unroll
        for (int ni = 0; ni < 4; ++ni) {
            const uint32_t b0 = bf[ni >> 1][(ni & 1) ? 1 : 0];
            const uint32_t b1 = bf[ni >> 1][(ni & 1) ? 3 : 2];
            MMA16816(acc[mi][ni], af[mi], b0, b1);
        }
    }
}

template <int MODE>
__global__ __launch_bounds__(256, 2)
void hgemm3_kernel(float* __restrict__ Oout)
{
    constexpr int LDA  = (MODE == 0) ? EDIM : KDIM;
    constexpr int LDB  = (MODE == 0) ? EDIM : KDIM;
    constexpr int LDC  = (MODE == 0) ? KDIM : EDIM;
    constexpr int KTOT = (MODE == 0) ? EDIM : KDIM;
    constexpr int KCH  = (MODE == 0) ? 32 : 64;
    constexpr size_t SA = (MODE == 0) ? (size_t)QDIM * EDIM : (size_t)QDIM * KDIM;
    constexpr size_t SB = (MODE == 0) ? (size_t)KDIM * EDIM : (size_t)EDIM * KDIM;
    constexpr size_t SC = (MODE == 0) ? (size_t)QDIM * KDIM : (size_t)QDIM * EDIM;
    constexpr int NITER  = KTOT / KCH;            // 16 / 32
    constexpr int NSTAGE = (MODE == 0) ? 3 : 2;
    constexpr int DEPTH  = NSTAGE - 1;

    // Stage layouts
    constexpr uint32_t OFF_A  = 0;                // MODE0: A-pack; MODE1: Ph
    constexpr uint32_t OFF_B  = TILE16K;          // MODE0: B-pack; MODE1: Vh
    constexpr uint32_t OFF_BL = 2 * TILE16K;      // MODE1 only: Vl
    constexpr uint32_t STAGE  = (MODE == 0) ? 2 * TILE16K : 3 * TILE16K;

    extern __shared__ __align__(256) uint8_t smem[];
    const uint32_t sb = smem_u32(smem);

    const int tid  = threadIdx.x;
    const int lane = tid & 31;
    const int wid  = tid >> 5;                   // 0..7
    const int wm   = (wid >> 2) * 64;            // 0 or 64
    const int wn   = (wid & 3) * 32;             // 0..96
    const int b    = blockIdx.z;
    const int m0   = blockIdx.y * 128;
    const int n0   = blockIdx.x * 128;

    const fp16* Ah = ((MODE == 0) ? g_Qh : g_Ph)  + b * SA + (size_t)m0 * LDA;
    const fp16* Al = g_Ql + b * SA + (size_t)m0 * LDA;          // MODE 0 only
    const fp16* Bh = ((MODE == 0) ? g_Kh : g_Vth) + b * SB + (size_t)n0 * LDB;
    const fp16* Bl = ((MODE == 0) ? g_Kl : g_Vtl) + b * SB + (size_t)n0 * LDB;
    float* C = ((MODE == 0) ? g_E : Oout) + b * SC;

    float acc[4][4][4];
    #pragma unroll
    for (int i = 0; i < 4; i++)
        #pragma unroll
        for (int j = 0; j < 4; j++)
            #pragma unroll
            for (int q = 0; q < 4; q++) acc[i][j][q] = 0.0f;

    const int a_r15 = lane & 15;
    const int c_hi  = lane >> 4;

    // Fill one stage with chunk 'ck'
    auto fill = [&](int stage, int ck) {
        const uint32_t st = sb + (uint32_t)stage * STAGE;
        const int k0 = ck * KCH;
        if (MODE == 0) {
            cp_pack(st + OFF_A, Ah + k0, Al + k0, LDA, tid);
            cp_pack(st + OFF_B, Bh + k0, Bl + k0, LDB, tid);
        } else {
            cp_tile(st + OFF_A,  Ah + k0, LDA, tid);
            cp_tile(st + OFF_B,  Bh + k0, LDB, tid);
            cp_tile(st + OFF_BL, Bl + k0, LDB, tid);
        }
        CP_COMMIT();
    };

    // Prologue: fill DEPTH stages
    #pragma unroll
    for (int d = 0; d < DEPTH; ++d) fill(d, d);

    for (int it = 0; it < NITER; ++it) {
        if (it + DEPTH <= NITER) {               // chunks still pending
            if (DEPTH == 2 && it + 2 <= NITER && it + 1 < NITER) CP_WAIT1();
            else CP_WAIT0();
        }
        __syncthreads();                         // chunk it visible; stage
                                                 // (it+DEPTH)%NSTAGE drained
        if (it + DEPTH < NITER) fill((it + DEPTH) % NSTAGE, it + DEPTH);

        const uint32_t SBASE = sb + (uint32_t)(it % NSTAGE) * STAGE;

        if (MODE == 0) {
            #pragma unroll
            for (int kk = 0; kk < 2; ++kk) {     // two k16 steps in chunk of 32
                uint32_t af[4][4], bfh[2][4], bfl[2][4];
                lds_a(SBASE + OFF_A, kk * 2,     wm, a_r15, c_hi, af);   // A hi
                lds_b(SBASE + OFF_B, kk * 2,     wn, a_r15, c_hi, bfh);  // B hi
                lds_b(SBASE + OFF_B, 4 + kk * 2, wn, a_r15, c_hi, bfl);  // B lo
                mma_step(acc, af, bfh);                                   // Ah*Bh
                mma_step(acc, af, bfl);                                   // Ah*Bl
                lds_a(SBASE + OFF_A, 4 + kk * 2, wm, a_r15, c_hi, af);   // A lo
                mma_step(acc, af, bfh);                                   // Al*Bh
            }
        } else {
            #pragma unroll
            for (int kk = 0; kk < 4; ++kk) {     // four k16 steps in chunk of 64
                uint32_t af[4][4], bfh[2][4], bfl[2][4];
                lds_a(SBASE + OFF_A,  kk * 2, wm, a_r15, c_hi, af);   // Ph
                lds_b(SBASE + OFF_B,  kk * 2, wn, a_r15, c_hi, bfh);  // Vh
                lds_b(SBASE + OFF_BL, kk * 2, wn, a_r15, c_hi, bfl);  // Vl
                mma_step(acc, af, bfh);                                // P*Vh
                mma_step(acc, af, bfl);                                // P*Vl
            }
        }
    }
    CP_WAIT0();

    // Epilogue
    const int g  = lane >> 2;
    const int ti = lane & 3;
    #pragma unroll
    for (int mi = 0; mi < 4; ++mi) {
        #pragma unroll
        for (int ni = 0; ni < 4; ++ni) {
            const int row = m0 + wm + mi * 16 + g;
            const int col = n0 + wn + ni * 8 + ti * 2;
            *(float2*)&C[(size_t)row * LDC + col] =
                make_float2(acc[mi][ni][0], acc[mi][ni][1]);
            *(float2*)&C[(size_t)(row + 8) * LDC + col] =
                make_float2(acc[mi][ni][2], acc[mi][ni][3]);
        }
    }
}

// ---------------------------------------------------------------------------
extern "C" void kernel_launch(void* const* d_in, const int* in_sizes, int n_in,
                              void* d_out, int out_size)
{
    const float* Q = (const float*)d_in[0];
    const float* K = (const float*)d_in[1];
    const float* V = (const float*)d_in[2];
    float*       O = (float*)d_out;

    // Both modes: 96KB smem per CTA (2 CTAs/SM = 192KB)
    cudaFuncSetAttribute(hgemm3_kernel<0>, cudaFuncAttributeMaxDynamicSharedMemorySize, 98304);
    cudaFuncSetAttribute(hgemm3_kernel<1>, cudaFuncAttributeMaxDynamicSharedMemorySize, 98304);

    const int n4 = NB * QDIM * EDIM / 4;
    split_kernel<<<(n4 + 255) / 256, 256>>>(Q, 0, n4);
    split_kernel<<<(n4 + 255) / 256, 256>>>(K, 1, n4);
    vtrans_kernel<<<dim3(KDIM / 32, EDIM / 32, NB), 256>>>(V);

    hgemm3_kernel<0><<<dim3(KDIM / 128, QDIM / 128, NB), 256, 98304>>>(nullptr);

    softmax_split_kernel<<<NB * QDIM, 256>>>();

    hgemm3_kernel<1><<<dim3(EDIM / 128, QDIM / 128, NB), 256, 98304>>>(O);
}

// round 11
// speedup vs baseline: 1.5715x; 1.0009x over previous
#include <cuda_runtime.h>
#include <cuda_fp16.h>
#include <cstdint>

#define NB   8
#define QDIM 2048
#define KDIM 2048
#define EDIM 512

typedef __half fp16;

// ---------------------------------------------------------------------------
// Device-global scratch (allocation-guard-safe)
// ---------------------------------------------------------------------------
__device__ __align__(256) fp16  g_Qh[(size_t)NB * QDIM * EDIM];
__device__ __align__(256) fp16  g_Ql[(size_t)NB * QDIM * EDIM];
__device__ __align__(256) fp16  g_Kh[(size_t)NB * KDIM * EDIM];
__device__ __align__(256) fp16  g_Kl[(size_t)NB * KDIM * EDIM];
__device__ __align__(256) fp16  g_Vth[(size_t)NB * EDIM * KDIM];  // V^T [b][e][k]
__device__ __align__(256) fp16  g_Vtl[(size_t)NB * EDIM * KDIM];
__device__ __align__(256) float g_E  [(size_t)NB * QDIM * KDIM];  // logits
__device__ __align__(256) fp16  g_Ph [(size_t)NB * QDIM * KDIM];  // softmax (hi only)

// ---------------------------------------------------------------------------
// PTX helpers (plain sm_80+ features only — virtual arch is compute_103)
// ---------------------------------------------------------------------------
__device__ __forceinline__ uint32_t smem_u32(const void* p) {
    uint32_t a;
    asm("{ .reg .u64 t; cvta.to.shared.u64 t, %1; cvt.u32.u64 %0, t; }" : "=r"(a) : "l"(p));
    return a;
}

__device__ __forceinline__ uint32_t h2_u32(__half2 h) {
    union { __half2 h; uint32_t u; } c;
    c.h = h;
    return c.u;
}

#define CP_ASYNC16(dst, src) \
    asm volatile("cp.async.cg.shared.global [%0], [%1], 16;" :: "r"(dst), "l"(src))
#define CP_COMMIT() asm volatile("cp.async.commit_group;" ::: "memory")
#define CP_WAIT1()  asm volatile("cp.async.wait_group 1;" ::: "memory")
#define CP_WAIT0()  asm volatile("cp.async.wait_group 0;" ::: "memory")

#define LDSM_X4(r0, r1, r2, r3, a)                                          \
    asm volatile("ldmatrix.sync.aligned.m8n8.x4.shared.b16 {%0,%1,%2,%3}, [%4];" \
        : "=r"(r0), "=r"(r1), "=r"(r2), "=r"(r3) : "r"(a))

#define MMA16816(d, a, b0, b1)                                              \
    asm volatile("mma.sync.aligned.m16n8k16.row.col.f32.f16.f16.f32 "       \
        "{%0,%1,%2,%3},{%4,%5,%6,%7},{%8,%9},{%0,%1,%2,%3};"                \
        : "+f"((d)[0]), "+f"((d)[1]), "+f"((d)[2]), "+f"((d)[3])            \
        : "r"((a)[0]), "r"((a)[1]), "r"((a)[2]), "r"((a)[3]),               \
          "r"(b0), "r"(b1))

// ---------------------------------------------------------------------------
// Elementwise fp32 -> fp16 hi/lo split  (which: 0 = Q, 1 = K)
// ---------------------------------------------------------------------------
__global__ __launch_bounds__(256)
void split_kernel(const float* __restrict__ X, int which, int n4)
{
    fp16* Xh = which ? g_Kh : g_Qh;
    fp16* Xl = which ? g_Kl : g_Ql;
    int i = blockIdx.x * 256 + threadIdx.x;
    if (i >= n4) return;
    float4 v = ((const float4*)X)[i];
    fp16 h0 = __float2half_rn(v.x), h1 = __float2half_rn(v.y);
    fp16 h2 = __float2half_rn(v.z), h3 = __float2half_rn(v.w);
    fp16 l0 = __float2half_rn(v.x - __half2float(h0));
    fp16 l1 = __float2half_rn(v.y - __half2float(h1));
    fp16 l2 = __float2half_rn(v.z - __half2float(h2));
    fp16 l3 = __float2half_rn(v.w - __half2float(h3));
    ((__half2*)Xh)[2 * i]     = __half2(h0, h1);
    ((__half2*)Xh)[2 * i + 1] = __half2(h2, h3);
    ((__half2*)Xl)[2 * i]     = __half2(l0, l1);
    ((__half2*)Xl)[2 * i + 1] = __half2(l2, l3);
}

// ---------------------------------------------------------------------------
// V [b][k][e] fp32 -> V^T [b][e][k] fp16 hi/lo
// ---------------------------------------------------------------------------
__global__ __launch_bounds__(256)
void vtrans_kernel(const float* __restrict__ V)
{
    __shared__ float t[32][33];
    const int b  = blockIdx.z;
    const int k0 = blockIdx.x * 32;
    const int e0 = blockIdx.y * 32;
    const int tx = threadIdx.x & 31;
    const int ty = threadIdx.x >> 5;
    const float* Vb = V + (size_t)b * KDIM * EDIM;

    #pragma unroll
    for (int j = 0; j < 4; j++)
        t[ty + j * 8][tx] = Vb[(size_t)(k0 + ty + j * 8) * EDIM + e0 + tx];
    __syncthreads();

    #pragma unroll
    for (int j = 0; j < 4; j++) {
        int e = e0 + ty + j * 8;
        int k = k0 + tx;
        float x = t[tx][ty + j * 8];
        fp16 h = __float2half_rn(x);
        fp16 l = __float2half_rn(x - __half2float(h));
        size_t o = (size_t)b * EDIM * KDIM + (size_t)e * KDIM + k;
        g_Vth[o] = h;
        g_Vtl[o] = l;
    }
}

// ---------------------------------------------------------------------------
// Row softmax of g_E -> fp16 (hi only) in g_Ph  (float4 I/O)
// ---------------------------------------------------------------------------
__global__ __launch_bounds__(256)
void softmax_split_kernel()
{
    const size_t row = blockIdx.x;
    const float* p = g_E + row * (size_t)KDIM;
    const int tid = threadIdx.x;

    float4 va = ((const float4*)p)[tid];
    float4 vb = ((const float4*)p)[tid + 256];

    float m = fmaxf(fmaxf(fmaxf(va.x, va.y), fmaxf(va.z, va.w)),
                    fmaxf(fmaxf(vb.x, vb.y), fmaxf(vb.z, vb.w)));

    __shared__ float red[8];
    #pragma unroll
    for (int off = 16; off > 0; off >>= 1) m = fmaxf(m, __shfl_xor_sync(~0u, m, off));
    if ((tid & 31) == 0) red[tid >> 5] = m;
    __syncthreads();
    if (tid < 8) {
        float t = red[tid];
        #pragma unroll
        for (int off = 4; off > 0; off >>= 1) t = fmaxf(t, __shfl_xor_sync(0xFFu, t, off));
        red[tid] = t;
    }
    __syncthreads();
    m = red[0];

    va.x = __expf(va.x - m); va.y = __expf(va.y - m);
    va.z = __expf(va.z - m); va.w = __expf(va.w - m);
    vb.x = __expf(vb.x - m); vb.y = __expf(vb.y - m);
    vb.z = __expf(vb.z - m); vb.w = __expf(vb.w - m);
    float s = (va.x + va.y) + (va.z + va.w) + (vb.x + vb.y) + (vb.z + vb.w);

    __shared__ float red2[8];
    #pragma unroll
    for (int off = 16; off > 0; off >>= 1) s += __shfl_xor_sync(~0u, s, off);
    if ((tid & 31) == 0) red2[tid >> 5] = s;
    __syncthreads();
    if (tid < 8) {
        float t = red2[tid];
        #pragma unroll
        for (int off = 4; off > 0; off >>= 1) t += __shfl_xor_sync(0xFFu, t, off);
        red2[tid] = t;
    }
    __syncthreads();
    const float inv = 1.0f / red2[0];

    fp16* ph = g_Ph + row * (size_t)KDIM;
    __half2 hh[4];
    hh[0] = __half2(__float2half_rn(va.x * inv), __float2half_rn(va.y * inv));
    hh[1] = __half2(__float2half_rn(va.z * inv), __float2half_rn(va.w * inv));
    hh[2] = __half2(__float2half_rn(vb.x * inv), __float2half_rn(vb.y * inv));
    hh[3] = __half2(__float2half_rn(vb.z * inv), __float2half_rn(vb.w * inv));
    *(uint2*)&ph[tid * 4]        = make_uint2(h2_u32(hh[0]), h2_u32(hh[1]));
    *(uint2*)&ph[1024 + tid * 4] = make_uint2(h2_u32(hh[2]), h2_u32(hh[3]));
}

// ---------------------------------------------------------------------------
// HMMA split-fp16 GEMM: 2 CTAs/SM + pipelined cp.async ring (coalesced fills).
//   MODE 0 (3 passes): E = Q.K^T. K-chunk 32. Packed rows: 128B = [hi32|lo32].
//   MODE 1 (2 passes): O = P.V.  K-chunk 64. Tiles Ph / Vh / Vl, 128B rows.
// CTA tile 128x128, 256 threads (8 warps, 2x4), warp tile 64x32,
// __launch_bounds__(256,2) -> 2 CTAs/SM. 96KB smem/CTA both modes.
// (Structure plateaued at tensor ~62% — issue-slot bound; unchanged this round.)
// ---------------------------------------------------------------------------
#define TILE16K 16384u

__device__ __forceinline__ void cp_pack(uint32_t dstbase, const fp16* srcH,
                                        const fp16* srcL, int ld, int tid)
{
    const char* sh = (const char*)srcH;
    const char* sl = (const char*)srcL;
    const size_t row_bytes = (size_t)ld * 2;
    #pragma unroll
    for (int p = 0; p < 4; ++p) {
        int idx = tid + p * 256;                 // 0..1023
        int r = idx >> 3;                        // row 0..127
        int c = idx & 7;                         // chunk 0..7
        const char* src = (c < 4) ? sh + (size_t)r * row_bytes + c * 16
                                  : sl + (size_t)r * row_bytes + (c - 4) * 16;
        uint32_t dst = dstbase + (uint32_t)r * 128u + (uint32_t)((c ^ (r & 7)) << 4);
        CP_ASYNC16(dst, src);
    }
}

__device__ __forceinline__ void cp_tile(uint32_t dstbase, const fp16* src,
                                        int ld, int tid)
{
    const char* s = (const char*)src;
    const size_t row_bytes = (size_t)ld * 2;
    const int c = tid & 7;
    #pragma unroll
    for (int r0 = 0; r0 < 128; r0 += 32) {
        int r = r0 + (tid >> 3);
        uint32_t dst = dstbase + (uint32_t)r * 128u + (uint32_t)((c ^ (r & 7)) << 4);
        CP_ASYNC16(dst, s + (size_t)r * row_bytes + c * 16);
    }
}

__device__ __forceinline__ void lds_a(uint32_t base, int cbase, int wm,
                                      int a_r15, int c_hi, uint32_t af[4][4])
{
    #pragma unroll
    for (int mi = 0; mi < 4; ++mi) {
        const int row = wm + mi * 16 + a_r15;
        const uint32_t addr = base + (uint32_t)row * 128u
            + (uint32_t)(((cbase + c_hi) ^ (row & 7)) << 4);
        LDSM_X4(af[mi][0], af[mi][1], af[mi][2], af[mi][3], addr);
    }
}

__device__ __forceinline__ void lds_b(uint32_t base, int cbase, int wn,
                                      int a_r15, int c_hi, uint32_t bf[2][4])
{
    #pragma unroll
    for (int nj = 0; nj < 2; ++nj) {
        const int row = wn + nj * 16 + a_r15;
        const uint32_t addr = base + (uint32_t)row * 128u
            + (uint32_t)(((cbase + c_hi) ^ (row & 7)) << 4);
        LDSM_X4(bf[nj][0], bf[nj][1], bf[nj][2], bf[nj][3], addr);
    }
}

__device__ __forceinline__ void mma_step(float acc[4][4][4],
                                         uint32_t af[4][4], uint32_t bf[2][4])
{
    #pragma unroll
    for (int mi = 0; mi < 4; ++mi) {
        #pragma unroll
        for (int ni = 0; ni < 4; ++ni) {
            const uint32_t b0 = bf[ni >> 1][(ni & 1) ? 1 : 0];
            const uint32_t b1 = bf[ni >> 1][(ni & 1) ? 3 : 2];
            MMA16816(acc[mi][ni], af[mi], b0, b1);
        }
    }
}

template <int MODE>
__global__ __launch_bounds__(256, 2)
void hgemm3_kernel(float* __restrict__ Oout)
{
    constexpr int LDA  = (MODE == 0) ? EDIM : KDIM;
    constexpr int LDB  = (MODE == 0) ? EDIM : KDIM;
    constexpr int LDC  = (MODE == 0) ? KDIM : EDIM;
    constexpr int KTOT = (MODE == 0) ? EDIM : KDIM;
    constexpr int KCH  = (MODE == 0) ? 32 : 64;
    constexpr size_t SA = (MODE == 0) ? (size_t)QDIM * EDIM : (size_t)QDIM * KDIM;
    constexpr size_t SB = (MODE == 0) ? (size_t)KDIM * EDIM : (size_t)EDIM * KDIM;
    constexpr size_t SC = (MODE == 0) ? (size_t)QDIM * KDIM : (size_t)QDIM * EDIM;
    constexpr int NITER  = KTOT / KCH;            // 16 / 32
    constexpr int NSTAGE = (MODE == 0) ? 3 : 2;
    constexpr int DEPTH  = NSTAGE - 1;

    constexpr uint32_t OFF_A  = 0;
    constexpr uint32_t OFF_B  = TILE16K;
    constexpr uint32_t OFF_BL = 2 * TILE16K;      // MODE 1 only
    constexpr uint32_t STAGE  = (MODE == 0) ? 2 * TILE16K : 3 * TILE16K;

    extern __shared__ __align__(256) uint8_t smem[];
    const uint32_t sb = smem_u32(smem);

    const int tid  = threadIdx.x;
    const int lane = tid & 31;
    const int wid  = tid >> 5;
    const int wm   = (wid >> 2) * 64;
    const int wn   = (wid & 3) * 32;
    const int b    = blockIdx.z;
    const int m0   = blockIdx.y * 128;
    const int n0   = blockIdx.x * 128;

    const fp16* Ah = ((MODE == 0) ? g_Qh : g_Ph)  + b * SA + (size_t)m0 * LDA;
    const fp16* Al = g_Ql + b * SA + (size_t)m0 * LDA;
    const fp16* Bh = ((MODE == 0) ? g_Kh : g_Vth) + b * SB + (size_t)n0 * LDB;
    const fp16* Bl = ((MODE == 0) ? g_Kl : g_Vtl) + b * SB + (size_t)n0 * LDB;
    float* C = ((MODE == 0) ? g_E : Oout) + b * SC;

    float acc[4][4][4];
    #pragma unroll
    for (int i = 0; i < 4; i++)
        #pragma unroll
        for (int j = 0; j < 4; j++)
            #pragma unroll
            for (int q = 0; q < 4; q++) acc[i][j][q] = 0.0f;

    const int a_r15 = lane & 15;
    const int c_hi  = lane >> 4;

    auto fill = [&](int stage, int ck) {
        const uint32_t st = sb + (uint32_t)stage * STAGE;
        const int k0 = ck * KCH;
        if (MODE == 0) {
            cp_pack(st + OFF_A, Ah + k0, Al + k0, LDA, tid);
            cp_pack(st + OFF_B, Bh + k0, Bl + k0, LDB, tid);
        } else {
            cp_tile(st + OFF_A,  Ah + k0, LDA, tid);
            cp_tile(st + OFF_B,  Bh + k0, LDB, tid);
            cp_tile(st + OFF_BL, Bl + k0, LDB, tid);
        }
        CP_COMMIT();
    };

    #pragma unroll
    for (int d = 0; d < DEPTH; ++d) fill(d, d);

    for (int it = 0; it < NITER; ++it) {
        if (it + DEPTH <= NITER) {
            if (DEPTH == 2 && it + 2 <= NITER && it + 1 < NITER) CP_WAIT1();
            else CP_WAIT0();
        }
        __syncthreads();
        if (it + DEPTH < NITER) fill((it + DEPTH) % NSTAGE, it + DEPTH);

        const uint32_t SBASE = sb + (uint32_t)(it % NSTAGE) * STAGE;

        if (MODE == 0) {
            #pragma unroll
            for (int kk = 0; kk < 2; ++kk) {
                uint32_t af[4][4], bfh[2][4], bfl[2][4];
                lds_a(SBASE + OFF_A, kk * 2,     wm, a_r15, c_hi, af);
                lds_b(SBASE + OFF_B, kk * 2,     wn, a_r15, c_hi, bfh);
                lds_b(SBASE + OFF_B, 4 + kk * 2, wn, a_r15, c_hi, bfl);
                mma_step(acc, af, bfh);
                mma_step(acc, af, bfl);
                lds_a(SBASE + OFF_A, 4 + kk * 2, wm, a_r15, c_hi, af);
                mma_step(acc, af, bfh);
            }
        } else {
            #pragma unroll
            for (int kk = 0; kk < 4; ++kk) {
                uint32_t af[4][4], bfh[2][4], bfl[2][4];
                lds_a(SBASE + OFF_A,  kk * 2, wm, a_r15, c_hi, af);
                lds_b(SBASE + OFF_B,  kk * 2, wn, a_r15, c_hi, bfh);
                lds_b(SBASE + OFF_BL, kk * 2, wn, a_r15, c_hi, bfl);
                mma_step(acc, af, bfh);
                mma_step(acc, af, bfl);
            }
        }
    }
    CP_WAIT0();

    const int g  = lane >> 2;
    const int ti = lane & 3;
    #pragma unroll
    for (int mi = 0; mi < 4; ++mi) {
        #pragma unroll
        for (int ni = 0; ni < 4; ++ni) {
            const int row = m0 + wm + mi * 16 + g;
            const int col = n0 + wn + ni * 8 + ti * 2;
            *(float2*)&C[(size_t)row * LDC + col] =
                make_float2(acc[mi][ni][0], acc[mi][ni][1]);
            *(float2*)&C[(size_t)(row + 8) * LDC + col] =
                make_float2(acc[mi][ni][2], acc[mi][ni][3]);
        }
    }
}

// ---------------------------------------------------------------------------
// Launch: fork a side stream so V-prep (vtrans) overlaps the compute-bound
// QK GEMM + softmax. Event fork/join keeps everything in one captured graph.
// ---------------------------------------------------------------------------
extern "C" void kernel_launch(void* const* d_in, const int* in_sizes, int n_in,
                              void* d_out, int out_size)
{
    const float* Q = (const float*)d_in[0];
    const float* K = (const float*)d_in[1];
    const float* V = (const float*)d_in[2];
    float*       O = (float*)d_out;

    // One-time host-side resources (created on the first, uncaptured call).
    static cudaStream_t s_side = nullptr;
    static cudaEvent_t  s_fork = nullptr, s_join = nullptr;
    if (s_side == nullptr) {
        cudaStreamCreateWithFlags(&s_side, cudaStreamNonBlocking);
        cudaEventCreateWithFlags(&s_fork, cudaEventDisableTiming);
        cudaEventCreateWithFlags(&s_join, cudaEventDisableTiming);
    }

    cudaFuncSetAttribute(hgemm3_kernel<0>, cudaFuncAttributeMaxDynamicSharedMemorySize, 98304);
    cudaFuncSetAttribute(hgemm3_kernel<1>, cudaFuncAttributeMaxDynamicSharedMemorySize, 98304);

    // Fork: side stream does V-prep concurrently with Q/K split + QK + softmax.
    cudaEventRecord(s_fork, 0);
    cudaStreamWaitEvent(s_side, s_fork, 0);
    vtrans_kernel<<<dim3(KDIM / 32, EDIM / 32, NB), 256, 0, s_side>>>(V);
    cudaEventRecord(s_join, s_side);

    const int n4 = NB * QDIM * EDIM / 4;
    split_kernel<<<(n4 + 255) / 256, 256>>>(Q, 0, n4);
    split_kernel<<<(n4 + 255) / 256, 256>>>(K, 1, n4);

    hgemm3_kernel<0><<<dim3(KDIM / 128, QDIM / 128, NB), 256, 98304>>>(nullptr);

    softmax_split_kernel<<<NB * QDIM, 256>>>();

    // Join: PV needs V^T hi/lo.
    cudaStreamWaitEvent(0, s_join, 0);
    hgemm3_kernel<1><<<dim3(EDIM / 128, QDIM / 128, NB), 256, 98304>>>(O);
}